// round 9
// baseline (speedup 1.0000x reference)
#include <cuda_runtime.h>
#include <cuda_bf16.h>

// ConformerAttention: B=8, S=1024, D=512, H=8, hd=64, P=2047
// rel_shift identity: shifted[i,j] = raw[i, j + (S-1) - i] -> p row r = 1023 + j - i.

#define CB 8
#define CS 1024
#define CD 512
#define CH 8
#define CHD 64
#define CP 2047
#define MTOK (CB*CS)   // 8192

typedef __nv_bfloat16 bf16;

__device__ __forceinline__ unsigned pack_bf2(float lo, float hi) {
    unsigned r; asm("cvt.rn.bf16x2.f32 %0, %1, %2;" : "=r"(r) : "f"(hi), "f"(lo)); return r;
}
__device__ __forceinline__ float bf_lo(unsigned u) { return __uint_as_float(u << 16); }
__device__ __forceinline__ float bf_hi(unsigned u) { return __uint_as_float(u & 0xFFFF0000u); }

__device__ __forceinline__ void mma16(float4& c, unsigned a0, unsigned a1, unsigned a2, unsigned a3,
                                      unsigned b0, unsigned b1) {
    asm volatile(
        "mma.sync.aligned.m16n8k16.row.col.f32.bf16.bf16.f32 "
        "{%0,%1,%2,%3}, {%4,%5,%6,%7}, {%8,%9}, {%0,%1,%2,%3};"
        : "+f"(c.x), "+f"(c.y), "+f"(c.z), "+f"(c.w)
        : "r"(a0), "r"(a1), "r"(a2), "r"(a3), "r"(b0), "r"(b1));
}
__device__ __forceinline__ unsigned sptr(const void* p) {
    return (unsigned)__cvta_generic_to_shared(p);
}
__device__ __forceinline__ void ldsm_x4(unsigned* r, unsigned addr) {
    asm volatile("ldmatrix.sync.aligned.m8n8.x4.shared.b16 {%0,%1,%2,%3}, [%4];"
        : "=r"(r[0]), "=r"(r[1]), "=r"(r[2]), "=r"(r[3]) : "r"(addr));
}
__device__ __forceinline__ void ldsm_x2(unsigned& r0, unsigned& r1, unsigned addr) {
    asm volatile("ldmatrix.sync.aligned.m8n8.x2.shared.b16 {%0,%1}, [%2];"
        : "=r"(r0), "=r"(r1) : "r"(addr));
}
__device__ __forceinline__ void cpa16(unsigned dst, const void* src) {
    asm volatile("cp.async.cg.shared.global [%0], [%1], 16;" :: "r"(dst), "l"(src));
}
#define CP_COMMIT() asm volatile("cp.async.commit_group;")
#define CP_WAIT1()  asm volatile("cp.async.wait_group 1;")
#define CP_WAIT0()  asm volatile("cp.async.wait_group 0;")

// -------- scratch (allocation-free: device globals) --------
__device__ bf16 g_h [MTOK*CD];
__device__ bf16 g_q [CB*CH*CS*CHD];      // [bh][S][hd]
__device__ bf16 g_k [CB*CH*CS*CHD];      // [bh][S][hd]
__device__ bf16 g_v [CB*CH*CS*CHD];      // [bh][hd][S]  (pre-transposed, mode 5)
__device__ bf16 g_p [CH*CP*CHD];         // [H][P][hd]
__device__ bf16 g_ao[MTOK*CD];           // [B,S,D]
__device__ bf16 g_wq[CD*CD], g_wk[CD*CD], g_wv[CD*CD], g_wo[CD*CD], g_wp[CD*CD];
__device__ bf16 g_pe[CP*CD];             // pos_emb bf16

// ============================ fp32 -> bf16 conversions ============================
__global__ void __launch_bounds__(256) wconv_kernel(
    const float* __restrict__ w0, const float* __restrict__ w1, const float* __restrict__ w2,
    const float* __restrict__ w3, const float* __restrict__ w4,
    bf16* __restrict__ d0, bf16* __restrict__ d1, bf16* __restrict__ d2,
    bf16* __restrict__ d3, bf16* __restrict__ d4)
{
    int y = blockIdx.y;
    const float* s = (y == 0) ? w0 : (y == 1) ? w1 : (y == 2) ? w2 : (y == 3) ? w3 : w4;
    bf16* d        = (y == 0) ? d0 : (y == 1) ? d1 : (y == 2) ? d2 : (y == 3) ? d3 : d4;
    int i = blockIdx.x * 256 + threadIdx.x;     // 8 floats per thread, 512*512/8 = 32768
    float4 f0 = *((const float4*)s + i * 2);
    float4 f1 = *((const float4*)s + i * 2 + 1);
    *(uint4*)(d + i * 8) = make_uint4(pack_bf2(f0.x, f0.y), pack_bf2(f0.z, f0.w),
                                      pack_bf2(f1.x, f1.y), pack_bf2(f1.z, f1.w));
}
__global__ void __launch_bounds__(256) peconv_kernel(const float* __restrict__ s, bf16* __restrict__ d, int n8)
{
    int i = blockIdx.x * 256 + threadIdx.x;
    if (i >= n8) return;
    float4 f0 = *((const float4*)s + i * 2);
    float4 f1 = *((const float4*)s + i * 2 + 1);
    *(uint4*)(d + i * 8) = make_uint4(pack_bf2(f0.x, f0.y), pack_bf2(f0.z, f0.w),
                                      pack_bf2(f1.x, f1.y), pack_bf2(f1.z, f1.w));
}

// ============================ LayerNorm (fp32 in -> bf16 out) ============================
__global__ void __launch_bounds__(128) ln_kernel(const float* __restrict__ x,
    const float* __restrict__ w, const float* __restrict__ b, bf16* __restrict__ out)
{
    int row = blockIdx.x;
    int t = threadIdx.x;
    const float* xr = x + (size_t)row * CD;
    float4 v = *(const float4*)(xr + t * 4);
    float s = v.x + v.y + v.z + v.w;
    #pragma unroll
    for (int o = 16; o; o >>= 1) s += __shfl_xor_sync(0xffffffffu, s, o);
    __shared__ float ws1[4], ws2[4];
    if ((t & 31) == 0) ws1[t >> 5] = s;
    __syncthreads();
    float mean = (ws1[0] + ws1[1] + ws1[2] + ws1[3]) * (1.0f / 512.0f);
    float dx = v.x - mean, dy = v.y - mean, dz = v.z - mean, dw = v.w - mean;
    float q = dx*dx + dy*dy + dz*dz + dw*dw;
    #pragma unroll
    for (int o = 16; o; o >>= 1) q += __shfl_xor_sync(0xffffffffu, q, o);
    if ((t & 31) == 0) ws2[t >> 5] = q;
    __syncthreads();
    float var = (ws2[0] + ws2[1] + ws2[2] + ws2[3]) * (1.0f / 512.0f);
    float rstd = rsqrtf(var + 1e-5f);
    float4 wv = *(const float4*)(w + t * 4);
    float4 bv = *(const float4*)(b + t * 4);
    float ox = dx * rstd * wv.x + bv.x;
    float oy = dy * rstd * wv.y + bv.y;
    float oz = dz * rstd * wv.z + bv.z;
    float ow = dw * rstd * wv.w + bv.w;
    *(uint2*)(out + (size_t)row * CD + t * 4) = make_uint2(pack_bf2(ox, oy), pack_bf2(oz, ow));
}

// ============================ GEMM core (bf16 mma + ldmatrix + cp.async pipeline) ============================
constexpr int GST = 128 * 72;    // elems per stage buffer

__device__ __forceinline__ void gemm_core(
    const bf16* __restrict__ A, int M,
    const bf16* __restrict__ W,
    const float* __restrict__ bias,
    const float* __restrict__ resid,
    void* __restrict__ outp, int mode,
    bf16* As, bf16* Ws)              // each 2*GST elems
{
    const int tid = threadIdx.x;
    const int l = tid & 31, wid = tid >> 5;
    const int wm = wid >> 1, wn = wid & 1;
    const int m0 = blockIdx.y * 128, n0 = blockIdx.x * 128;
    const int gid = l >> 2, tig = l & 3;
    const int lr = l & 7;
    const int a_row = ((l >> 3) & 1) * 8 + lr;
    const int a_col = (l >> 4) * 8;
    const int b_col = ((l >> 3) & 1) * 8;

    float4 cacc[2][8];
    #pragma unroll
    for (int mt = 0; mt < 2; mt++)
        #pragma unroll
        for (int nt = 0; nt < 8; nt++) cacc[mt][nt] = make_float4(0.f, 0.f, 0.f, 0.f);

    const unsigned aA = sptr(As) + ((wm * 32 + a_row) * 72 + a_col) * 2;
    const unsigned aB = sptr(Ws) + ((wn * 64 + lr) * 72 + b_col) * 2;
    const int srow = tid >> 1;                 // staging: 2 threads per row, 4 rows-groups
    const int sseg = (tid & 1) * 4;            // segs 0-3 / 4-7

    // stage(k0, buf): 128 rows x 64 k, A and W
    auto stage = [&](int k0, int buf) {
        #pragma unroll
        for (int it = 0; it < 4; it++) {
            int seg = sseg + it;
            int am = m0 + srow; if (am >= M) am = M - 1;
            cpa16(sptr(As) + (buf * GST + srow * 72 + seg * 8) * 2,
                  A + (size_t)am * 512 + k0 + seg * 8);
            cpa16(sptr(Ws) + (buf * GST + srow * 72 + seg * 8) * 2,
                  W + (size_t)(n0 + srow) * 512 + k0 + seg * 8);
        }
        CP_COMMIT();
    };

    stage(0, 0);
    for (int c = 0; c < 8; c++) {
        if (c < 7) { stage((c + 1) * 64, (c + 1) & 1); CP_WAIT1(); }
        else CP_WAIT0();
        __syncthreads();
        unsigned off = (unsigned)(c & 1) * (GST * 2);
        #pragma unroll
        for (int ks = 0; ks < 4; ks++) {
            unsigned a0[4], a1[4];
            ldsm_x4(a0, aA + off + ks * 32);
            ldsm_x4(a1, aA + off + 16 * 144 + ks * 32);
            #pragma unroll
            for (int nt = 0; nt < 8; nt++) {
                unsigned b0, b1;
                ldsm_x2(b0, b1, aB + off + nt * 8 * 144 + ks * 32);
                mma16(cacc[0][nt], a0[0], a0[1], a0[2], a0[3], b0, b1);
                mma16(cacc[1][nt], a1[0], a1[1], a1[2], a1[3], b0, b1);
            }
        }
        __syncthreads();
    }

    #pragma unroll
    for (int mt = 0; mt < 2; mt++) {
        #pragma unroll
        for (int nt = 0; nt < 8; nt++) {
            float4 c = cacc[mt][nt];
            int r0 = m0 + wm * 32 + mt * 16 + gid;
            int c0 = n0 + wn * 64 + nt * 8 + tig * 2;
            float vals[4] = {c.x, c.y, c.z, c.w};
            #pragma unroll
            for (int e = 0; e < 4; e++) {
                int m = r0 + (e >= 2 ? 8 : 0);
                int n = c0 + (e & 1);
                float val = vals[e];
                if (mode == 0) {
                    int bi = m >> 10, sr = m & 1023;
                    ((bf16*)outp)[((size_t)(bi * CH + (n >> 6)) << 16) + ((size_t)sr << 6) + (n & 63)]
                        = __float2bfloat16(val + bias[n]);
                } else if (mode == 5) {
                    int bi = m >> 10, sr = m & 1023;
                    ((bf16*)outp)[((size_t)(bi * CH + (n >> 6)) << 16) + (size_t)(n & 63) * 1024 + sr]
                        = __float2bfloat16(val + bias[n]);
                } else if (mode == 3) {
                    if (m < M)
                        ((bf16*)outp)[((size_t)(n >> 6) * CP + m) * 64 + (n & 63)]
                            = __float2bfloat16(val);
                } else {
                    size_t idx = (size_t)m * 512 + n;
                    ((float*)outp)[idx] = val + bias[n] + resid[idx];
                }
            }
        }
    }
}

constexpr int GSM_B = 2 * GST * 2 * 2;     // 73728 bytes dynamic

__global__ void __launch_bounds__(256, 2) gemm_kernel(
    const bf16* __restrict__ Ap, int M,
    const bf16* __restrict__ W, const float* __restrict__ bias,
    const float* __restrict__ resid, void* __restrict__ outp, int mode)
{
    extern __shared__ bf16 gsm[];
    gemm_core(Ap, M, W, bias, resid, outp, mode, gsm, gsm + 2 * GST);
}

__global__ void __launch_bounds__(256, 2) qkv_kernel(
    const bf16* __restrict__ A,
    const bf16* __restrict__ Wq, const bf16* __restrict__ Wk, const bf16* __restrict__ Wv,
    const float* __restrict__ bq, const float* __restrict__ bk, const float* __restrict__ bv,
    bf16* __restrict__ q, bf16* __restrict__ k, bf16* __restrict__ v)
{
    extern __shared__ bf16 gsm[];
    int z = blockIdx.z;
    const bf16* W     = (z == 0) ? Wq : (z == 1) ? Wk : Wv;
    const float* bias = (z == 0) ? bq : (z == 1) ? bk : bv;
    bf16* o           = (z == 0) ? q  : (z == 1) ? k  : v;
    gemm_core(A, MTOK, W, bias, nullptr, o, (z == 2) ? 5 : 0, gsm, gsm + 2 * GST);
}

// ============================ Fused attention (bf16 scores, cp.async pipeline) ============================
constexpr int SCH    = 1080;               // bf16 score stride (135*16B rows: ldsm conflict-free)
constexpr int SC_E   = 32 * SCH;           // 34560
constexpr int QT_E   = 32 * 72;            // 2304 each
constexpr int KB_E   = 128 * 72;           // 9216 per buffer (Vt 64*136=8704 fits)
constexpr int ASM_B  = (SC_E + 2 * QT_E + 2 * KB_E) * 2;   // 115,200 bytes -> 2 CTAs/SM

__global__ void __launch_bounds__(256, 2) attn_kernel(const float* __restrict__ bu,
    const float* __restrict__ bvp, bf16* __restrict__ ao)
{
    extern __shared__ bf16 smb[];
    bf16* sc   = smb;                  // [32][1080] bf16 scores/probs
    bf16* qut  = smb + SC_E;           // [32][72]
    bf16* qvt  = qut + QT_E;           // [32][72]
    bf16* kbuf = qvt + QT_E;           // 2 x [128][72] (Vt 2 x [64][136])

    const int tid = threadIdx.x;
    const int w = tid >> 5, l = tid & 31;
    const int gid = l >> 2, tig = l & 3;
    const int lr = l & 7;
    const int a_row = ((l >> 3) & 1) * 8 + lr;
    const int a_col = (l >> 4) * 8;
    const int b_col = ((l >> 3) & 1) * 8;
    const int qt = blockIdx.x & 31;
    const int bh = blockIdx.x >> 5;
    const int h  = bh & 7, b = bh >> 3;
    const int i0 = qt * 32;
    const bf16* qbase = g_q + (size_t)bh * (CS * CHD);
    const bf16* kbase = g_k + (size_t)bh * (CS * CHD);
    const bf16* vbase = g_v + (size_t)bh * (CS * CHD);   // [64][1024]
    const bf16* pbase = g_p + (size_t)h  * (CP * CHD);

    const unsigned kb_sp = sptr(kbuf);
    constexpr unsigned KBB = KB_E * 2;                   // buffer stride bytes
    const int srow = tid >> 1;                           // staging K/P: 2 thr/row
    const int sseg = (tid & 1) * 4;
    const int rlo = 992 - i0;

    // ---- Phase A: q tile [32][72] bf16, both bias variants ----
    {
        int ii = tid >> 3, dq = (tid & 7) * 8;
        uint4 qw = *(const uint4*)(qbase + (size_t)(i0 + ii) * 64 + dq);
        unsigned wsv[4] = {qw.x, qw.y, qw.z, qw.w};
        unsigned uo[4], vo[4];
        #pragma unroll
        for (int j = 0; j < 4; j++) {
            float fx = bf_lo(wsv[j]), fy = bf_hi(wsv[j]);
            int d = dq + 2 * j;
            uo[j] = pack_bf2(fx + bu [h*64+d], fy + bu [h*64+d+1]);
            vo[j] = pack_bf2(fx + bvp[h*64+d], fy + bvp[h*64+d+1]);
        }
        *(uint4*)&qut[ii * 72 + dq] = make_uint4(uo[0], uo[1], uo[2], uo[3]);
        *(uint4*)&qvt[ii * 72 + dq] = make_uint4(vo[0], vo[1], vo[2], vo[3]);
    }

    const unsigned aQU = sptr(qut) + (a_row * 72 + a_col) * 2;
    const unsigned aQV = sptr(qvt) + (a_row * 72 + a_col) * 2;
    const unsigned aKB = kb_sp + ((w * 16 + lr) * 72 + b_col) * 2;

    // staging helpers (row-chunk of 128 x 64 bf16)
    auto stageP = [&](int ch, int buf) {
        int r = rlo + ch * 128 + srow; if (r > 2046) r = 2046;
        const bf16* src = pbase + (size_t)r * 64;
        #pragma unroll
        for (int it = 0; it < 4; it++) {
            int seg = sseg + it;
            cpa16(kb_sp + buf * KBB + (srow * 72 + seg * 8) * 2, src + seg * 8);
        }
        CP_COMMIT();
    };
    auto stageK = [&](int ch, int buf) {
        const bf16* src = kbase + (size_t)(ch * 128 + srow) * 64;
        #pragma unroll
        for (int it = 0; it < 4; it++) {
            int seg = sseg + it;
            cpa16(kb_sp + buf * KBB + (srow * 72 + seg * 8) * 2, src + seg * 8);
        }
        CP_COMMIT();
    };

    // Phase A data must be visible before mma
    __syncthreads();

    // ======== Phase B1: pos scores over band (9 chunks of 128), sheared assign ========
    stageP(0, 0);
    #pragma unroll 1
    for (int ch = 0; ch < 9; ch++) {
        if (ch < 8) { stageP(ch + 1, (ch + 1) & 1); CP_WAIT1(); }
        else CP_WAIT0();
        __syncthreads();
        unsigned off = (unsigned)(ch & 1) * KBB;
        float4 cacc[2][2];
        #pragma unroll
        for (int mt = 0; mt < 2; mt++)
            #pragma unroll
            for (int nt = 0; nt < 2; nt++) cacc[mt][nt] = make_float4(0.f,0.f,0.f,0.f);
        #pragma unroll
        for (int ks = 0; ks < 4; ks++) {
            unsigned a0[4], a1[4];
            ldsm_x4(a0, aQV + ks * 32);
            ldsm_x4(a1, aQV + 16 * 144 + ks * 32);
            #pragma unroll
            for (int nt = 0; nt < 2; nt++) {
                unsigned b0, b1;
                ldsm_x2(b0, b1, aKB + off + nt * 8 * 144 + ks * 32);
                mma16(cacc[0][nt], a0[0], a0[1], a0[2], a0[3], b0, b1);
                mma16(cacc[1][nt], a1[0], a1[1], a1[2], a1[3], b0, b1);
            }
        }
        if (ch == 0 || ch == 8) {
            #pragma unroll
            for (int mt = 0; mt < 2; mt++) {
                #pragma unroll
                for (int nt = 0; nt < 2; nt++) {
                    float4 c = cacc[mt][nt];
                    int ii = mt * 16 + gid;
                    int rr = ch * 128 + w * 16 + nt * 8 + tig * 2;
                    int jx = rr + ii - 31;
                    if (jx >= 0 && jx < 1024)         sc[ii * SCH + jx]     = __float2bfloat16(c.x);
                    if (jx + 1 >= 0 && jx + 1 < 1024) sc[ii * SCH + jx + 1] = __float2bfloat16(c.y);
                    int jz = jx + 8, i2 = ii + 8;
                    if (jz >= 0 && jz < 1024)         sc[i2 * SCH + jz]     = __float2bfloat16(c.z);
                    if (jz + 1 >= 0 && jz + 1 < 1024) sc[i2 * SCH + jz + 1] = __float2bfloat16(c.w);
                }
            }
        } else {
            #pragma unroll
            for (int mt = 0; mt < 2; mt++) {
                #pragma unroll
                for (int nt = 0; nt < 2; nt++) {
                    float4 c = cacc[mt][nt];
                    int ii = mt * 16 + gid;
                    int jx = ch * 128 + w * 16 + nt * 8 + tig * 2 + ii - 31;
                    sc[ii * SCH + jx]           = __float2bfloat16(c.x);
                    sc[ii * SCH + jx + 1]       = __float2bfloat16(c.y);
                    sc[(ii + 8) * SCH + jx + 8] = __float2bfloat16(c.z);
                    sc[(ii + 8) * SCH + jx + 9] = __float2bfloat16(c.w);
                }
            }
        }
        __syncthreads();
    }

    // ======== Phase B2: content scores (8 chunks of 128), add in place (bf16 RMW) ========
    stageK(0, 0);
    #pragma unroll 1
    for (int ch = 0; ch < 8; ch++) {
        if (ch < 7) { stageK(ch + 1, (ch + 1) & 1); CP_WAIT1(); }
        else CP_WAIT0();
        __syncthreads();
        unsigned off = (unsigned)(ch & 1) * KBB;
        float4 cacc[2][2];
        #pragma unroll
        for (int mt = 0; mt < 2; mt++)
            #pragma unroll
            for (int nt = 0; nt < 2; nt++) cacc[mt][nt] = make_float4(0.f,0.f,0.f,0.f);
        #pragma unroll
        for (int ks = 0; ks < 4; ks++) {
            unsigned a0[4], a1[4];
            ldsm_x4(a0, aQU + ks * 32);
            ldsm_x4(a1, aQU + 16 * 144 + ks * 32);
            #pragma unroll
            for (int nt = 0; nt < 2; nt++) {
                unsigned b0, b1;
                ldsm_x2(b0, b1, aKB + off + nt * 8 * 144 + ks * 32);
                mma16(cacc[0][nt], a0[0], a0[1], a0[2], a0[3], b0, b1);
                mma16(cacc[1][nt], a1[0], a1[1], a1[2], a1[3], b0, b1);
            }
        }
        #pragma unroll
        for (int mt = 0; mt < 2; mt++) {
            #pragma unroll
            for (int nt = 0; nt < 2; nt++) {
                float4 c = cacc[mt][nt];
                int ii = mt * 16 + gid;
                int col = ch * 128 + w * 16 + nt * 8 + tig * 2;
                unsigned* p0 = (unsigned*)&sc[ii * SCH + col];
                unsigned u0 = *p0;
                *p0 = pack_bf2(bf_lo(u0) + c.x, bf_hi(u0) + c.y);
                unsigned* p1 = (unsigned*)&sc[(ii + 8) * SCH + col];
                unsigned u1 = *p1;
                *p1 = pack_bf2(bf_lo(u1) + c.z, bf_hi(u1) + c.w);
            }
        }
        __syncthreads();
    }

    // ======== Phase C: softmax (scale 1/8 inside exp), 4 rows per warp ========
    #pragma unroll
    for (int rr = 0; rr < 4; rr++) {
        int row = w * 4 + rr;
        bf16* rp = sc + row * SCH;
        unsigned u[16];
        float f[32];
        #pragma unroll
        for (int g = 0; g < 4; g++) {
            uint4 q4 = *(const uint4*)(rp + g * 256 + l * 8);
            u[g*4+0] = q4.x; u[g*4+1] = q4.y; u[g*4+2] = q4.z; u[g*4+3] = q4.w;
        }
        float mx = -1e30f;
        #pragma unroll
        for (int e = 0; e < 16; e++) {
            f[2*e]   = bf_lo(u[e]);
            f[2*e+1] = bf_hi(u[e]);
            mx = fmaxf(mx, fmaxf(f[2*e], f[2*e+1]));
        }
        #pragma unroll
        for (int o = 16; o; o >>= 1) mx = fmaxf(mx, __shfl_xor_sync(0xffffffffu, mx, o));
        float sum = 0.f;
        #pragma unroll
        for (int e = 0; e < 32; e++) {
            f[e] = __expf((f[e] - mx) * 0.125f);
            sum += f[e];
        }
        #pragma unroll
        for (int o = 16; o; o >>= 1) sum += __shfl_xor_sync(0xffffffffu, sum, o);
        float inv = 1.0f / sum;
        #pragma unroll
        for (int g = 0; g < 4; g++) {
            uint4 q4;
            q4.x = pack_bf2(f[g*8+0] * inv, f[g*8+1] * inv);
            q4.y = pack_bf2(f[g*8+2] * inv, f[g*8+3] * inv);
            q4.z = pack_bf2(f[g*8+4] * inv, f[g*8+5] * inv);
            q4.w = pack_bf2(f[g*8+6] * inv, f[g*8+7] * inv);
            *(uint4*)(rp + g * 256 + l * 8) = q4;
        }
    }
    __syncthreads();

    // ======== Phase D: O = attn @ V (8 chunks of 128 keys), 8-way k-split ========
    bf16* Vt = kbuf;                                   // 2 x [64][136]
    const int vrow = tid >> 2;                         // staging V: 4 thr/row (64 rows)
    const int vseg = (tid & 3) * 4;
    auto stageV = [&](int ch, int buf) {
        const bf16* src = vbase + (size_t)vrow * 1024 + ch * 128;
        #pragma unroll
        for (int it = 0; it < 4; it++) {
            int seg = vseg + it;
            cpa16(kb_sp + buf * KBB + (vrow * 136 + seg * 8) * 2, src + seg * 8);
        }
        CP_COMMIT();
    };

    float4 oacc[2][8];
    #pragma unroll
    for (int mt = 0; mt < 2; mt++)
        #pragma unroll
        for (int nt = 0; nt < 8; nt++) oacc[mt][nt] = make_float4(0.f,0.f,0.f,0.f);

    stageV(0, 0);
    #pragma unroll 1
    for (int ch = 0; ch < 8; ch++) {
        if (ch < 7) { stageV(ch + 1, (ch + 1) & 1); CP_WAIT1(); }
        else CP_WAIT0();
        __syncthreads();
        unsigned off = (unsigned)(ch & 1) * KBB;
        unsigned a0[4], a1[4];
        ldsm_x4(a0, sptr(sc) + (a_row * SCH + ch * 128 + w * 16 + a_col) * 2);
        ldsm_x4(a1, sptr(sc) + ((16 + a_row) * SCH + ch * 128 + w * 16 + a_col) * 2);
        #pragma unroll
        for (int nt = 0; nt < 8; nt++) {
            unsigned b0, b1;
            ldsm_x2(b0, b1, kb_sp + off + ((nt * 8 + lr) * 136 + w * 16 + b_col) * 2);
            mma16(oacc[0][nt], a0[0], a0[1], a0[2], a0[3], b0, b1);
            mma16(oacc[1][nt], a1[0], a1[1], a1[2], a1[3], b0, b1);
        }
        __syncthreads();
    }

    // per-warp partials -> fp32 overlay over sc/qut (dead), then cross-warp reduce
    float* ovl = (float*)sc;
    {
        float* pb = ovl + w * 2176;
        #pragma unroll
        for (int mt = 0; mt < 2; mt++) {
            #pragma unroll
            for (int nt = 0; nt < 8; nt++) {
                float4 c = oacc[mt][nt];
                int r = mt * 16 + gid;
                int cc = nt * 8 + tig * 2;
                pb[r * 68 + cc]           = c.x;
                pb[r * 68 + cc + 1]       = c.y;
                pb[(r + 8) * 68 + cc]     = c.z;
                pb[(r + 8) * 68 + cc + 1] = c.w;
            }
        }
    }
    __syncthreads();
    #pragma unroll
    for (int rep = 0; rep < 2; rep++) {
        int e = tid + rep * 256;
        int row = e >> 4, d4 = (e & 15) * 4;
        float4 s = make_float4(0.f, 0.f, 0.f, 0.f);
        #pragma unroll
        for (int ww = 0; ww < 8; ww++) {
            float4 p4 = *(const float4*)&ovl[ww * 2176 + row * 68 + d4];
            s.x += p4.x; s.y += p4.y; s.z += p4.z; s.w += p4.w;
        }
        *(uint2*)(ao + (size_t)(b * 1024 + i0 + row) * 512 + h * 64 + d4)
            = make_uint2(pack_bf2(s.x, s.y), pack_bf2(s.z, s.w));
    }
}

// ============================ launch ============================
extern "C" void kernel_launch(void* const* d_in, const int* in_sizes, int n_in,
                              void* d_out, int out_size)
{
    const float* x       = (const float*)d_in[0];
    const float* pos_emb = (const float*)d_in[1];
    const float* ln_w    = (const float*)d_in[2];
    const float* ln_b    = (const float*)d_in[3];
    const float* Wq      = (const float*)d_in[4];
    const float* bq      = (const float*)d_in[5];
    const float* Wk      = (const float*)d_in[6];
    const float* bk      = (const float*)d_in[7];
    const float* Wv      = (const float*)d_in[8];
    const float* bv      = (const float*)d_in[9];
    const float* Wo      = (const float*)d_in[10];
    const float* bo      = (const float*)d_in[11];
    const float* Wp      = (const float*)d_in[12];
    const float* pbu     = (const float*)d_in[13];
    const float* pbv     = (const float*)d_in[14];
    float* out = (float*)d_out;

    bf16 *hp, *qp, *kp, *vp, *pp, *aop;
    bf16 *wqp, *wkp, *wvp, *wop, *wpp, *pep;
    cudaGetSymbolAddress((void**)&hp,  g_h);
    cudaGetSymbolAddress((void**)&qp,  g_q);
    cudaGetSymbolAddress((void**)&kp,  g_k);
    cudaGetSymbolAddress((void**)&vp,  g_v);
    cudaGetSymbolAddress((void**)&pp,  g_p);
    cudaGetSymbolAddress((void**)&aop, g_ao);
    cudaGetSymbolAddress((void**)&wqp, g_wq);
    cudaGetSymbolAddress((void**)&wkp, g_wk);
    cudaGetSymbolAddress((void**)&wvp, g_wv);
    cudaGetSymbolAddress((void**)&wop, g_wo);
    cudaGetSymbolAddress((void**)&wpp, g_wp);
    cudaGetSymbolAddress((void**)&pep, g_pe);

    cudaFuncSetAttribute(attn_kernel, cudaFuncAttributeMaxDynamicSharedMemorySize, ASM_B);
    cudaFuncSetAttribute(gemm_kernel, cudaFuncAttributeMaxDynamicSharedMemorySize, GSM_B);
    cudaFuncSetAttribute(qkv_kernel,  cudaFuncAttributeMaxDynamicSharedMemorySize, GSM_B);

    wconv_kernel<<<dim3(128, 5), 256>>>(Wq, Wk, Wv, Wo, Wp, wqp, wkp, wvp, wop, wpp);
    peconv_kernel<<<512, 256>>>(pos_emb, pep, CP * CD / 8);
    ln_kernel<<<MTOK, 128>>>(x, ln_w, ln_b, hp);

    qkv_kernel<<<dim3(4, 64, 3), 256, GSM_B>>>(hp, wqp, wkp, wvp, bq, bk, bv, qp, kp, vp);
    gemm_kernel<<<dim3(4, 16), 256, GSM_B>>>(pep, CP, wpp, nullptr, nullptr, pp, 3);

    attn_kernel<<<CB * CH * (CS / 32), 256, ASM_B>>>(pbu, pbv, aop);

    gemm_kernel<<<dim3(4, 64), 256, GSM_B>>>(aop, MTOK, wop, bo, x, out, 4);
}

// round 10
// speedup vs baseline: 1.1146x; 1.1146x over previous
#include <cuda_runtime.h>
#include <cuda_bf16.h>

// ConformerAttention: B=8, S=1024, D=512, H=8, hd=64, P=2047
// rel_shift identity: shifted[i,j] = raw[i, j + (S-1) - i] -> p row r = 1023 + j - i.
// 64-row q tiles: rlo = 960 - i0, j = rr + ii - 63.

#define CB 8
#define CS 1024
#define CD 512
#define CH 8
#define CHD 64
#define CP 2047
#define MTOK (CB*CS)   // 8192

typedef __nv_bfloat16 bf16;

__device__ __forceinline__ unsigned pack_bf2(float lo, float hi) {
    unsigned r; asm("cvt.rn.bf16x2.f32 %0, %1, %2;" : "=r"(r) : "f"(hi), "f"(lo)); return r;
}
__device__ __forceinline__ float bf_lo(unsigned u) { return __uint_as_float(u << 16); }
__device__ __forceinline__ float bf_hi(unsigned u) { return __uint_as_float(u & 0xFFFF0000u); }

__device__ __forceinline__ void mma16(float4& c, unsigned a0, unsigned a1, unsigned a2, unsigned a3,
                                      unsigned b0, unsigned b1) {
    asm volatile(
        "mma.sync.aligned.m16n8k16.row.col.f32.bf16.bf16.f32 "
        "{%0,%1,%2,%3}, {%4,%5,%6,%7}, {%8,%9}, {%0,%1,%2,%3};"
        : "+f"(c.x), "+f"(c.y), "+f"(c.z), "+f"(c.w)
        : "r"(a0), "r"(a1), "r"(a2), "r"(a3), "r"(b0), "r"(b1));
}
__device__ __forceinline__ unsigned sptr(const void* p) {
    return (unsigned)__cvta_generic_to_shared(p);
}
__device__ __forceinline__ void ldsm_x4(unsigned* r, unsigned addr) {
    asm volatile("ldmatrix.sync.aligned.m8n8.x4.shared.b16 {%0,%1,%2,%3}, [%4];"
        : "=r"(r[0]), "=r"(r[1]), "=r"(r[2]), "=r"(r[3]) : "r"(addr));
}
__device__ __forceinline__ void ldsm_x2(unsigned& r0, unsigned& r1, unsigned addr) {
    asm volatile("ldmatrix.sync.aligned.m8n8.x2.shared.b16 {%0,%1}, [%2];"
        : "=r"(r0), "=r"(r1) : "r"(addr));
}

// -------- scratch (allocation-free: device globals) --------
__device__ bf16 g_h [MTOK*CD];
__device__ bf16 g_q [CB*CH*CS*CHD];      // [bh][S][hd]
__device__ bf16 g_k [CB*CH*CS*CHD];      // [bh][S][hd]
__device__ bf16 g_v [CB*CH*CS*CHD];      // [bh][hd][S]  (pre-transposed, mode 5)
__device__ bf16 g_p [CH*CP*CHD];         // [H][P][hd]
__device__ bf16 g_ao[MTOK*CD];           // [B,S,D]
__device__ bf16 g_wq[CD*CD], g_wk[CD*CD], g_wv[CD*CD], g_wo[CD*CD], g_wp[CD*CD];
__device__ bf16 g_pe[CP*CD];             // pos_emb bf16

// ============================ fp32 -> bf16 conversions ============================
__global__ void __launch_bounds__(256) wconv_kernel(
    const float* __restrict__ w0, const float* __restrict__ w1, const float* __restrict__ w2,
    const float* __restrict__ w3, const float* __restrict__ w4,
    bf16* __restrict__ d0, bf16* __restrict__ d1, bf16* __restrict__ d2,
    bf16* __restrict__ d3, bf16* __restrict__ d4)
{
    int y = blockIdx.y;
    const float* s = (y == 0) ? w0 : (y == 1) ? w1 : (y == 2) ? w2 : (y == 3) ? w3 : w4;
    bf16* d        = (y == 0) ? d0 : (y == 1) ? d1 : (y == 2) ? d2 : (y == 3) ? d3 : d4;
    int i = blockIdx.x * 256 + threadIdx.x;
    float4 f0 = *((const float4*)s + i * 2);
    float4 f1 = *((const float4*)s + i * 2 + 1);
    *(uint4*)(d + i * 8) = make_uint4(pack_bf2(f0.x, f0.y), pack_bf2(f0.z, f0.w),
                                      pack_bf2(f1.x, f1.y), pack_bf2(f1.z, f1.w));
}
__global__ void __launch_bounds__(256) peconv_kernel(const float* __restrict__ s, bf16* __restrict__ d, int n8)
{
    int i = blockIdx.x * 256 + threadIdx.x;
    if (i >= n8) return;
    float4 f0 = *((const float4*)s + i * 2);
    float4 f1 = *((const float4*)s + i * 2 + 1);
    *(uint4*)(d + i * 8) = make_uint4(pack_bf2(f0.x, f0.y), pack_bf2(f0.z, f0.w),
                                      pack_bf2(f1.x, f1.y), pack_bf2(f1.z, f1.w));
}

// ============================ LayerNorm (fp32 in -> bf16 out) ============================
__global__ void __launch_bounds__(128) ln_kernel(const float* __restrict__ x,
    const float* __restrict__ w, const float* __restrict__ b, bf16* __restrict__ out)
{
    int row = blockIdx.x;
    int t = threadIdx.x;
    const float* xr = x + (size_t)row * CD;
    float4 v = *(const float4*)(xr + t * 4);
    float s = v.x + v.y + v.z + v.w;
    #pragma unroll
    for (int o = 16; o; o >>= 1) s += __shfl_xor_sync(0xffffffffu, s, o);
    __shared__ float ws1[4], ws2[4];
    if ((t & 31) == 0) ws1[t >> 5] = s;
    __syncthreads();
    float mean = (ws1[0] + ws1[1] + ws1[2] + ws1[3]) * (1.0f / 512.0f);
    float dx = v.x - mean, dy = v.y - mean, dz = v.z - mean, dw = v.w - mean;
    float q = dx*dx + dy*dy + dz*dz + dw*dw;
    #pragma unroll
    for (int o = 16; o; o >>= 1) q += __shfl_xor_sync(0xffffffffu, q, o);
    if ((t & 31) == 0) ws2[t >> 5] = q;
    __syncthreads();
    float var = (ws2[0] + ws2[1] + ws2[2] + ws2[3]) * (1.0f / 512.0f);
    float rstd = rsqrtf(var + 1e-5f);
    float4 wv = *(const float4*)(w + t * 4);
    float4 bv = *(const float4*)(b + t * 4);
    float ox = dx * rstd * wv.x + bv.x;
    float oy = dy * rstd * wv.y + bv.y;
    float oz = dz * rstd * wv.z + bv.z;
    float ow = dw * rstd * wv.w + bv.w;
    *(uint2*)(out + (size_t)row * CD + t * 4) = make_uint2(pack_bf2(ox, oy), pack_bf2(oz, ow));
}

// ============================ GEMM core: C = A @ W^T (bf16 mma + ldmatrix, register staging) ============================
__device__ __forceinline__ void gemm_core(
    const bf16* __restrict__ A, int M,
    const bf16* __restrict__ W,
    const float* __restrict__ bias,
    const float* __restrict__ resid,
    void* __restrict__ outp, int mode,
    bf16* As, bf16* Ws)
{
    const int tid = threadIdx.x;
    const int l = tid & 31, wid = tid >> 5;
    const int wm = wid >> 1, wn = wid & 1;
    const int m0 = blockIdx.y * 128, n0 = blockIdx.x * 128;
    const int gid = l >> 2, tig = l & 3;
    const int lr = l & 7;
    const int a_row = ((l >> 3) & 1) * 8 + lr;
    const int a_col = (l >> 4) * 8;
    const int b_col = ((l >> 3) & 1) * 8;

    float4 cacc[2][8];
    #pragma unroll
    for (int mt = 0; mt < 2; mt++)
        #pragma unroll
        for (int nt = 0; nt < 8; nt++) cacc[mt][nt] = make_float4(0.f, 0.f, 0.f, 0.f);

    const unsigned aA = sptr(As) + ((wm * 32 + a_row) * 72 + a_col) * 2;
    const unsigned aB = sptr(Ws) + ((wn * 64 + lr) * 72 + b_col) * 2;

    for (int k0 = 0; k0 < 512; k0 += 64) {
        __syncthreads();
        #pragma unroll
        for (int it = 0; it < 4; it++) {
            int idx = tid + it * 256;
            int row = idx >> 3, seg = idx & 7;
            int kk = k0 + seg * 8;
            int am = m0 + row; if (am >= M) am = M - 1;
            *(uint4*)&As[row * 72 + seg * 8] = *(const uint4*)(A + (size_t)am * 512 + kk);
            *(uint4*)&Ws[row * 72 + seg * 8] = *(const uint4*)(W + (size_t)(n0 + row) * 512 + kk);
        }
        __syncthreads();
        #pragma unroll
        for (int ks = 0; ks < 4; ks++) {
            unsigned a0[4], a1[4];
            ldsm_x4(a0, aA + ks * 32);
            ldsm_x4(a1, aA + 16 * 144 + ks * 32);
            #pragma unroll
            for (int nt = 0; nt < 8; nt++) {
                unsigned b0, b1;
                ldsm_x2(b0, b1, aB + nt * 8 * 144 + ks * 32);
                mma16(cacc[0][nt], a0[0], a0[1], a0[2], a0[3], b0, b1);
                mma16(cacc[1][nt], a1[0], a1[1], a1[2], a1[3], b0, b1);
            }
        }
    }

    #pragma unroll
    for (int mt = 0; mt < 2; mt++) {
        #pragma unroll
        for (int nt = 0; nt < 8; nt++) {
            float4 c = cacc[mt][nt];
            int r0 = m0 + wm * 32 + mt * 16 + gid;
            int c0 = n0 + wn * 64 + nt * 8 + tig * 2;
            float vals[4] = {c.x, c.y, c.z, c.w};
            #pragma unroll
            for (int e = 0; e < 4; e++) {
                int m = r0 + (e >= 2 ? 8 : 0);
                int n = c0 + (e & 1);
                float val = vals[e];
                if (mode == 0) {
                    int bi = m >> 10, sr = m & 1023;
                    ((bf16*)outp)[((size_t)(bi * CH + (n >> 6)) << 16) + ((size_t)sr << 6) + (n & 63)]
                        = __float2bfloat16(val + bias[n]);
                } else if (mode == 5) {
                    int bi = m >> 10, sr = m & 1023;
                    ((bf16*)outp)[((size_t)(bi * CH + (n >> 6)) << 16) + (size_t)(n & 63) * 1024 + sr]
                        = __float2bfloat16(val + bias[n]);
                } else if (mode == 3) {
                    if (m < M)
                        ((bf16*)outp)[((size_t)(n >> 6) * CP + m) * 64 + (n & 63)]
                            = __float2bfloat16(val);
                } else {
                    size_t idx = (size_t)m * 512 + n;
                    ((float*)outp)[idx] = val + bias[n] + resid[idx];
                }
            }
        }
    }
}

__global__ void __launch_bounds__(256, 2) gemm_kernel(
    const bf16* __restrict__ Ap, int M,
    const bf16* __restrict__ W, const float* __restrict__ bias,
    const float* __restrict__ resid, void* __restrict__ outp, int mode)
{
    __shared__ bf16 As[128 * 72];
    __shared__ bf16 Ws[128 * 72];
    gemm_core(Ap, M, W, bias, resid, outp, mode, As, Ws);
}

__global__ void __launch_bounds__(256, 2) qkv_kernel(
    const bf16* __restrict__ A,
    const bf16* __restrict__ Wq, const bf16* __restrict__ Wk, const bf16* __restrict__ Wv,
    const float* __restrict__ bq, const float* __restrict__ bk, const float* __restrict__ bv,
    bf16* __restrict__ q, bf16* __restrict__ k, bf16* __restrict__ v)
{
    __shared__ bf16 As[128 * 72];
    __shared__ bf16 Ws[128 * 72];
    int z = blockIdx.z;
    const bf16* W     = (z == 0) ? Wq : (z == 1) ? Wk : Wv;
    const float* bias = (z == 0) ? bq : (z == 1) ? bk : bv;
    bf16* o           = (z == 0) ? q  : (z == 1) ? k  : v;
    gemm_core(A, MTOK, W, bias, nullptr, o, (z == 2) ? 5 : 0, As, Ws);
}

// ============================ Fused attention: 64-query tiles, 512 threads ============================
constexpr int SCH    = 1080;               // bf16 score stride (135*16B rows: ldsm conflict-free)
constexpr int SC_E   = 64 * SCH;           // 69120
constexpr int QT_E   = 64 * 72;            // 4608 each
constexpr int KB_E   = 128 * 72;           // 9216 (Vt 64*136=8704 fits)
constexpr int ASM_B  = (SC_E + 2 * QT_E + KB_E) * 2;   // 175,104 bytes -> 1 CTA/SM, 16 warps

__global__ void __launch_bounds__(512, 1) attn_kernel(const float* __restrict__ bu,
    const float* __restrict__ bvp, bf16* __restrict__ ao)
{
    extern __shared__ bf16 smb[];
    bf16* sc   = smb;                  // [64][1080]
    bf16* qut  = smb + SC_E;           // [64][72]
    bf16* qvt  = qut + QT_E;           // [64][72]
    bf16* kbuf = qvt + QT_E;           // [128][72] K/P chunk; Vt [64][136]

    const int tid = threadIdx.x;
    const int w = tid >> 5, l = tid & 31;
    const int gid = l >> 2, tig = l & 3;
    const int lr = l & 7;
    const int a_row = ((l >> 3) & 1) * 8 + lr;
    const int a_col = (l >> 4) * 8;
    const int b_col = ((l >> 3) & 1) * 8;
    const int wm = w >> 3;             // m-half (rows wm*32..+31)
    const int wn = w & 7;              // n/k slice
    const int qt = blockIdx.x & 15;
    const int bh = blockIdx.x >> 4;
    const int h  = bh & 7, b = bh >> 3;
    const int i0 = qt * 64;
    const bf16* qbase = g_q + (size_t)bh * (CS * CHD);
    const bf16* kbase = g_k + (size_t)bh * (CS * CHD);
    const bf16* vbase = g_v + (size_t)bh * (CS * CHD);   // [64][1024]
    const bf16* pbase = g_p + (size_t)h  * (CP * CHD);

    // ---- Phase A: q tile [64][72] bf16, both bias variants ----
    {
        int ii = tid >> 3, dq = (tid & 7) * 8;
        uint4 qw = *(const uint4*)(qbase + (size_t)(i0 + ii) * 64 + dq);
        unsigned wsv[4] = {qw.x, qw.y, qw.z, qw.w};
        unsigned uo[4], vo[4];
        #pragma unroll
        for (int j = 0; j < 4; j++) {
            float fx = bf_lo(wsv[j]), fy = bf_hi(wsv[j]);
            int d = dq + 2 * j;
            uo[j] = pack_bf2(fx + bu [h*64+d], fy + bu [h*64+d+1]);
            vo[j] = pack_bf2(fx + bvp[h*64+d], fy + bvp[h*64+d+1]);
        }
        *(uint4*)&qut[ii * 72 + dq] = make_uint4(uo[0], uo[1], uo[2], uo[3]);
        *(uint4*)&qvt[ii * 72 + dq] = make_uint4(vo[0], vo[1], vo[2], vo[3]);
    }

    const unsigned aQU = sptr(qut) + ((wm * 32 + a_row) * 72 + a_col) * 2;
    const unsigned aQV = sptr(qvt) + ((wm * 32 + a_row) * 72 + a_col) * 2;
    const unsigned aKB = sptr(kbuf) + ((wn * 16 + lr) * 72 + b_col) * 2;
    const int rlo = 960 - i0;
    const int srow = tid >> 2;                 // K/P staging: 128 rows, 4 thr/row
    const int sseg = (tid & 3) * 2;

    // ======== Phase B1: pos scores over band (9 chunks of 128), sheared assign ========
    #pragma unroll 1
    for (int ch = 0; ch < 9; ch++) {
        __syncthreads();
        {
            int r = rlo + ch * 128 + srow; if (r > 2046) r = 2046;
            const bf16* src = pbase + (size_t)r * 64;
            #pragma unroll
            for (int it = 0; it < 2; it++) {
                int seg = sseg + it;
                *(uint4*)&kbuf[srow * 72 + seg * 8] = *(const uint4*)(src + seg * 8);
            }
        }
        __syncthreads();
        float4 cacc[2][2];
        #pragma unroll
        for (int mt = 0; mt < 2; mt++)
            #pragma unroll
            for (int nt = 0; nt < 2; nt++) cacc[mt][nt] = make_float4(0.f,0.f,0.f,0.f);
        #pragma unroll
        for (int ks = 0; ks < 4; ks++) {
            unsigned a0[4], a1[4];
            ldsm_x4(a0, aQV + ks * 32);
            ldsm_x4(a1, aQV + 16 * 144 + ks * 32);
            #pragma unroll
            for (int nt = 0; nt < 2; nt++) {
                unsigned b0, b1;
                ldsm_x2(b0, b1, aKB + nt * 8 * 144 + ks * 32);
                mma16(cacc[0][nt], a0[0], a0[1], a0[2], a0[3], b0, b1);
                mma16(cacc[1][nt], a1[0], a1[1], a1[2], a1[3], b0, b1);
            }
        }
        if (ch == 0 || ch == 8) {
            #pragma unroll
            for (int mt = 0; mt < 2; mt++) {
                #pragma unroll
                for (int nt = 0; nt < 2; nt++) {
                    float4 c = cacc[mt][nt];
                    int ii = wm * 32 + mt * 16 + gid;
                    int rr = ch * 128 + wn * 16 + nt * 8 + tig * 2;
                    int jx = rr + ii - 63;
                    if (jx >= 0 && jx < 1024)         sc[ii * SCH + jx]     = __float2bfloat16(c.x);
                    if (jx + 1 >= 0 && jx + 1 < 1024) sc[ii * SCH + jx + 1] = __float2bfloat16(c.y);
                    int jz = jx + 8, i2 = ii + 8;
                    if (jz >= 0 && jz < 1024)         sc[i2 * SCH + jz]     = __float2bfloat16(c.z);
                    if (jz + 1 >= 0 && jz + 1 < 1024) sc[i2 * SCH + jz + 1] = __float2bfloat16(c.w);
                }
            }
        } else {
            #pragma unroll
            for (int mt = 0; mt < 2; mt++) {
                #pragma unroll
                for (int nt = 0; nt < 2; nt++) {
                    float4 c = cacc[mt][nt];
                    int ii = wm * 32 + mt * 16 + gid;
                    int jx = ch * 128 + wn * 16 + nt * 8 + tig * 2 + ii - 63;
                    sc[ii * SCH + jx]           = __float2bfloat16(c.x);
                    sc[ii * SCH + jx + 1]       = __float2bfloat16(c.y);
                    sc[(ii + 8) * SCH + jx + 8] = __float2bfloat16(c.z);
                    sc[(ii + 8) * SCH + jx + 9] = __float2bfloat16(c.w);
                }
            }
        }
    }

    // ======== Phase B2: content scores (8 chunks of 128), add in place (bf16 RMW) ========
    #pragma unroll 1
    for (int ch = 0; ch < 8; ch++) {
        __syncthreads();
        {
            const bf16* src = kbase + (size_t)(ch * 128 + srow) * 64;
            #pragma unroll
            for (int it = 0; it < 2; it++) {
                int seg = sseg + it;
                *(uint4*)&kbuf[srow * 72 + seg * 8] = *(const uint4*)(src + seg * 8);
            }
        }
        __syncthreads();
        float4 cacc[2][2];
        #pragma unroll
        for (int mt = 0; mt < 2; mt++)
            #pragma unroll
            for (int nt = 0; nt < 2; nt++) cacc[mt][nt] = make_float4(0.f,0.f,0.f,0.f);
        #pragma unroll
        for (int ks = 0; ks < 4; ks++) {
            unsigned a0[4], a1[4];
            ldsm_x4(a0, aQU + ks * 32);
            ldsm_x4(a1, aQU + 16 * 144 + ks * 32);
            #pragma unroll
            for (int nt = 0; nt < 2; nt++) {
                unsigned b0, b1;
                ldsm_x2(b0, b1, aKB + nt * 8 * 144 + ks * 32);
                mma16(cacc[0][nt], a0[0], a0[1], a0[2], a0[3], b0, b1);
                mma16(cacc[1][nt], a1[0], a1[1], a1[2], a1[3], b0, b1);
            }
        }
        #pragma unroll
        for (int mt = 0; mt < 2; mt++) {
            #pragma unroll
            for (int nt = 0; nt < 2; nt++) {
                float4 c = cacc[mt][nt];
                int ii = wm * 32 + mt * 16 + gid;
                int col = ch * 128 + wn * 16 + nt * 8 + tig * 2;
                unsigned* p0 = (unsigned*)&sc[ii * SCH + col];
                unsigned u0 = *p0;
                *p0 = pack_bf2(bf_lo(u0) + c.x, bf_hi(u0) + c.y);
                unsigned* p1 = (unsigned*)&sc[(ii + 8) * SCH + col];
                unsigned u1 = *p1;
                *p1 = pack_bf2(bf_lo(u1) + c.z, bf_hi(u1) + c.w);
            }
        }
    }
    __syncthreads();

    // ======== Phase C: softmax (scale 1/8 inside exp), 4 rows per warp ========
    #pragma unroll
    for (int rr = 0; rr < 4; rr++) {
        int row = w * 4 + rr;
        bf16* rp = sc + row * SCH;
        unsigned u[16];
        float f[32];
        #pragma unroll
        for (int g = 0; g < 4; g++) {
            uint4 q4 = *(const uint4*)(rp + g * 256 + l * 8);
            u[g*4+0] = q4.x; u[g*4+1] = q4.y; u[g*4+2] = q4.z; u[g*4+3] = q4.w;
        }
        float mx = -1e30f;
        #pragma unroll
        for (int e = 0; e < 16; e++) {
            f[2*e]   = bf_lo(u[e]);
            f[2*e+1] = bf_hi(u[e]);
            mx = fmaxf(mx, fmaxf(f[2*e], f[2*e+1]));
        }
        #pragma unroll
        for (int o = 16; o; o >>= 1) mx = fmaxf(mx, __shfl_xor_sync(0xffffffffu, mx, o));
        float sum = 0.f;
        #pragma unroll
        for (int e = 0; e < 32; e++) {
            f[e] = __expf((f[e] - mx) * 0.125f);
            sum += f[e];
        }
        #pragma unroll
        for (int o = 16; o; o >>= 1) sum += __shfl_xor_sync(0xffffffffu, sum, o);
        float inv = 1.0f / sum;
        #pragma unroll
        for (int g = 0; g < 4; g++) {
            uint4 q4;
            q4.x = pack_bf2(f[g*8+0] * inv, f[g*8+1] * inv);
            q4.y = pack_bf2(f[g*8+2] * inv, f[g*8+3] * inv);
            q4.z = pack_bf2(f[g*8+4] * inv, f[g*8+5] * inv);
            q4.w = pack_bf2(f[g*8+6] * inv, f[g*8+7] * inv);
            *(uint4*)(rp + g * 256 + l * 8) = q4;
        }
    }

    // ======== Phase D: O = attn @ V (8 chunks of 128 keys); warp = (m-half, k-slice) ========
    bf16* Vt = kbuf;                                   // [64][136]
    const int vrow = tid >> 3;                         // V staging: 64 rows, 8 thr/row
    const int vseg = (tid & 7) * 2;
    float4 oacc[2][8];
    #pragma unroll
    for (int mt = 0; mt < 2; mt++)
        #pragma unroll
        for (int nt = 0; nt < 8; nt++) oacc[mt][nt] = make_float4(0.f,0.f,0.f,0.f);

    #pragma unroll 1
    for (int ch = 0; ch < 8; ch++) {
        __syncthreads();
        {
            const bf16* src = vbase + (size_t)vrow * 1024 + ch * 128;
            #pragma unroll
            for (int it = 0; it < 2; it++) {
                int seg = vseg + it;
                *(uint4*)&Vt[vrow * 136 + seg * 8] = *(const uint4*)(src + seg * 8);
            }
        }
        __syncthreads();
        unsigned a0[4], a1[4];
        ldsm_x4(a0, sptr(sc) + ((wm * 32 + a_row) * SCH + ch * 128 + wn * 16 + a_col) * 2);
        ldsm_x4(a1, sptr(sc) + ((wm * 32 + 16 + a_row) * SCH + ch * 128 + wn * 16 + a_col) * 2);
        #pragma unroll
        for (int nt = 0; nt < 8; nt++) {
            unsigned b0, b1;
            ldsm_x2(b0, b1, sptr(Vt) + ((nt * 8 + lr) * 136 + wn * 16 + b_col) * 2);
            mma16(oacc[0][nt], a0[0], a0[1], a0[2], a0[3], b0, b1);
            mma16(oacc[1][nt], a1[0], a1[1], a1[2], a1[3], b0, b1);
        }
    }

    // per-warp partials -> fp32 overlay over sc (probs dead): 16 buffers of [32][68]
    __syncthreads();
    float* ovl = (float*)smb;
    {
        float* pb = ovl + (wm * 8 + wn) * 2176;
        #pragma unroll
        for (int mt = 0; mt < 2; mt++) {
            #pragma unroll
            for (int nt = 0; nt < 8; nt++) {
                float4 c = oacc[mt][nt];
                int r = mt * 16 + gid;
                int cc = nt * 8 + tig * 2;
                pb[r * 68 + cc]           = c.x;
                pb[r * 68 + cc + 1]       = c.y;
                pb[(r + 8) * 68 + cc]     = c.z;
                pb[(r + 8) * 68 + cc + 1] = c.w;
            }
        }
    }
    __syncthreads();
    #pragma unroll
    for (int rep = 0; rep < 2; rep++) {
        int e = tid + rep * 512;
        int row = e >> 4, d4 = (e & 15) * 4;     // row 0..63
        int mh = row >> 5, r32 = row & 31;
        float4 s = make_float4(0.f, 0.f, 0.f, 0.f);
        #pragma unroll
        for (int wk = 0; wk < 8; wk++) {
            float4 p4 = *(const float4*)&ovl[(mh * 8 + wk) * 2176 + r32 * 68 + d4];
            s.x += p4.x; s.y += p4.y; s.z += p4.z; s.w += p4.w;
        }
        *(uint2*)(ao + (size_t)(b * 1024 + i0 + row) * 512 + h * 64 + d4)
            = make_uint2(pack_bf2(s.x, s.y), pack_bf2(s.z, s.w));
    }
}

// ============================ launch ============================
extern "C" void kernel_launch(void* const* d_in, const int* in_sizes, int n_in,
                              void* d_out, int out_size)
{
    const float* x       = (const float*)d_in[0];
    const float* pos_emb = (const float*)d_in[1];
    const float* ln_w    = (const float*)d_in[2];
    const float* ln_b    = (const float*)d_in[3];
    const float* Wq      = (const float*)d_in[4];
    const float* bq      = (const float*)d_in[5];
    const float* Wk      = (const float*)d_in[6];
    const float* bk      = (const float*)d_in[7];
    const float* Wv      = (const float*)d_in[8];
    const float* bv      = (const float*)d_in[9];
    const float* Wo      = (const float*)d_in[10];
    const float* bo      = (const float*)d_in[11];
    const float* Wp      = (const float*)d_in[12];
    const float* pbu     = (const float*)d_in[13];
    const float* pbv     = (const float*)d_in[14];
    float* out = (float*)d_out;

    bf16 *hp, *qp, *kp, *vp, *pp, *aop;
    bf16 *wqp, *wkp, *wvp, *wop, *wpp, *pep;
    cudaGetSymbolAddress((void**)&hp,  g_h);
    cudaGetSymbolAddress((void**)&qp,  g_q);
    cudaGetSymbolAddress((void**)&kp,  g_k);
    cudaGetSymbolAddress((void**)&vp,  g_v);
    cudaGetSymbolAddress((void**)&pp,  g_p);
    cudaGetSymbolAddress((void**)&aop, g_ao);
    cudaGetSymbolAddress((void**)&wqp, g_wq);
    cudaGetSymbolAddress((void**)&wkp, g_wk);
    cudaGetSymbolAddress((void**)&wvp, g_wv);
    cudaGetSymbolAddress((void**)&wop, g_wo);
    cudaGetSymbolAddress((void**)&wpp, g_wp);
    cudaGetSymbolAddress((void**)&pep, g_pe);

    cudaFuncSetAttribute(attn_kernel, cudaFuncAttributeMaxDynamicSharedMemorySize, ASM_B);

    wconv_kernel<<<dim3(128, 5), 256>>>(Wq, Wk, Wv, Wo, Wp, wqp, wkp, wvp, wop, wpp);
    peconv_kernel<<<512, 256>>>(pos_emb, pep, CP * CD / 8);
    ln_kernel<<<MTOK, 128>>>(x, ln_w, ln_b, hp);

    qkv_kernel<<<dim3(4, 64, 3), 256>>>(hp, wqp, wkp, wvp, bq, bk, bv, qp, kp, vp);
    gemm_kernel<<<dim3(4, 16), 256>>>(pep, CP, wpp, nullptr, nullptr, pp, 3);

    attn_kernel<<<CB * CH * (CS / 64), 512, ASM_B>>>(pbu, pbv, aop);

    gemm_kernel<<<dim3(4, 64), 256>>>(aop, MTOK, wop, bo, x, out, 4);
}